// round 8
// baseline (speedup 1.0000x reference)
#include <cuda_runtime.h>
#include <cuda_fp16.h>
#include <math.h>
#include <stdint.h>

#define DDIM    64
#define KCODES  2048
#define NPTS    32768
#define HW      1024
#define NBLK    256            // 8-code n-blocks
#define PTS_CTA 64             // points per CTA (4 warps x m16)
#define C1N     2.8e-3f        // 1.43 * 2^-9 : fp16 dot-error coefficient
#define ABSL    0.01f          // absolute slack (fp32 epilogue rounding)
#define FINF    3.402823e+38f

__device__ int      g_idx[NPTS];
__device__ float    g_esq[KCODES];
__device__ float2   g_epi[KCODES];              // (esq, C1N*||e||)
__device__ uint32_t g_bf[NBLK * 32 * 8];        // fp16 B fragments, per-lane order

// ---------------------------------------------------------------------------
static __device__ __forceinline__ unsigned long long enc_key(float dist, int code) {
    unsigned int u = __float_as_uint(dist);
    u = (u & 0x80000000u) ? ~u : (u | 0x80000000u);
    return ((unsigned long long)u << 32) | (unsigned)code;
}
static __device__ __forceinline__ uint32_t pack_h2(float lo, float hi) {
    return (uint32_t)__half_as_ushort(__float2half_rn(lo))
         | ((uint32_t)__half_as_ushort(__float2half_rn(hi)) << 16);
}
static __device__ __forceinline__ void mma16816(float& c0, float& c1, float& c2, float& c3,
                                                uint32_t a0, uint32_t a1, uint32_t a2,
                                                uint32_t a3, uint32_t b0, uint32_t b1) {
    asm("mma.sync.aligned.m16n8k16.row.col.f32.f16.f16.f32 "
        "{%0,%1,%2,%3}, {%4,%5,%6,%7}, {%8,%9}, {%0,%1,%2,%3};"
        : "+f"(c0), "+f"(c1), "+f"(c2), "+f"(c3)
        : "r"(a0), "r"(a1), "r"(a2), "r"(a3), "r"(b0), "r"(b1));
}

// ---------------------------------------------------------------------------
// Prep 1: per code — exact esq (validated sequential order) + bound coeffs
// ---------------------------------------------------------------------------
__global__ void prep_epi(const float* __restrict__ cb) {
    int k = blockIdx.x * blockDim.x + threadIdx.x;
    if (k >= KCODES) return;
    const float4* r = reinterpret_cast<const float4*>(cb + (size_t)k * DDIM);
    float4 v[16];
    #pragma unroll
    for (int i = 0; i < 16; ++i) v[i] = __ldg(&r[i]);
    float s = 0.f;
    #pragma unroll
    for (int i = 0; i < 16; ++i) {
        s = fmaf(v[i].x, v[i].x, s); s = fmaf(v[i].y, v[i].y, s);
        s = fmaf(v[i].z, v[i].z, s); s = fmaf(v[i].w, v[i].w, s);
    }
    g_esq[k] = s;
    g_epi[k] = make_float2(s, C1N * sqrtf(s));
}

// ---------------------------------------------------------------------------
// Prep 2: fp16 B fragments in per-(nblk,lane) order for mma m16n8k16 col-B
// ---------------------------------------------------------------------------
__global__ void prep_bf(const float* __restrict__ cb) {
    int t = blockIdx.x * blockDim.x + threadIdx.x;     // 0..8191
    if (t >= NBLK * 32) return;
    int lane = t & 31;
    int nblk = t >> 5;
    int code = nblk * 8 + (lane >> 2);
    int kq   = (lane & 3) * 2;
    const float* e = cb + (size_t)code * DDIM;
    uint32_t r[8];
    #pragma unroll
    for (int s = 0; s < 4; ++s) {
        int k0 = s * 16 + kq;
        r[2 * s]     = pack_h2(__ldg(&e[k0]),     __ldg(&e[k0 + 1]));
        r[2 * s + 1] = pack_h2(__ldg(&e[k0 + 8]), __ldg(&e[k0 + 9]));
    }
    uint4* dst = reinterpret_cast<uint4*>(g_bf + (size_t)t * 8);
    dst[0] = make_uint4(r[0], r[1], r[2], r[3]);
    dst[1] = make_uint4(r[4], r[5], r[6], r[7]);
}

// ---------------------------------------------------------------------------
// Main: fp16 mma screen + exact recheck. 128 thr = 4 warps, 64 points/CTA.
// ---------------------------------------------------------------------------
__global__ __launch_bounds__(128)
void vq_mma(const float* __restrict__ laten, const float* __restrict__ cb,
            float* __restrict__ out) {
    __shared__ float xs[DDIM * 65];            // [d][p], stride 65
    __shared__ float sxsq[PTS_CTA];
    __shared__ float sxn[PTS_CTA];
    __shared__ int   sflag[PTS_CTA];
    __shared__ int   scount;
    __shared__ unsigned long long skey;

    const int tid  = threadIdx.x;
    const int lane = tid & 31;
    const int w    = tid >> 5;
    const int g    = lane >> 2;
    const int q    = lane & 3;

    const int p0  = blockIdx.x * PTS_CTA;
    const int b   = p0 >> 10;
    const int hw0 = p0 & 1023;
    const float* lat_b = laten + (size_t)b * (DDIM * HW) + hw0;

    // stage x tile
    #pragma unroll
    for (int i = 0; i < 32; ++i) {
        int idx = tid + i * 128;               // 4096
        int d = idx >> 6, p = idx & 63;
        xs[d * 65 + p] = lat_b[d * HW + p];
    }
    if (tid == 0) scount = 0;
    __syncthreads();
    if (tid < PTS_CTA) {                        // exact xsq, sequential order
        float s = 0.f;
        #pragma unroll 8
        for (int d = 0; d < DDIM; ++d) {
            float v = xs[d * 65 + tid];
            s = fmaf(v, v, s);
        }
        sxsq[tid] = s;
        sxn[tid]  = sqrtf(s);
    }
    __syncthreads();

    // A fragments (fp16), rows r0 = w*16+g, r1 = r0+8
    const int r0 = w * 16 + g, r1 = r0 + 8;
    uint32_t a[4][4];
    #pragma unroll
    for (int s = 0; s < 4; ++s) {
        int k0 = s * 16 + q * 2;
        a[s][0] = pack_h2(xs[k0 * 65 + r0],       xs[(k0 + 1) * 65 + r0]);
        a[s][1] = pack_h2(xs[k0 * 65 + r1],       xs[(k0 + 1) * 65 + r1]);
        a[s][2] = pack_h2(xs[(k0 + 8) * 65 + r0], xs[(k0 + 9) * 65 + r0]);
        a[s][3] = pack_h2(xs[(k0 + 8) * 65 + r1], xs[(k0 + 9) * 65 + r1]);
    }
    const float xsq0 = sxsq[r0], xsq1 = sxsq[r1];
    const float xn0  = sxn[r0],  xn1  = sxn[r1];

    float T0 = FINF, T1 = FINF;
    float L0a = FINF, L1a = FINF, L0b = FINF, L1b = FINF;
    int   C0a = 0, C1a = 0, C0b = 0, C1b = 0;

    #pragma unroll 2
    for (int nb = 0; nb < NBLK; ++nb) {
        const uint4* bp = reinterpret_cast<const uint4*>(g_bf + (size_t)(nb * 32 + lane) * 8);
        uint4 B0 = __ldg(bp);
        uint4 B1 = __ldg(bp + 1);
        float4 ep = __ldg(reinterpret_cast<const float4*>(g_epi) + nb * 4 + q);
        // ep = (esq0, c1n0, esq1, c1n1) for codes nb*8+2q, nb*8+2q+1

        float c0 = 0.f, c1 = 0.f, c2 = 0.f, c3 = 0.f;
        mma16816(c0, c1, c2, c3, a[0][0], a[0][1], a[0][2], a[0][3], B0.x, B0.y);
        mma16816(c0, c1, c2, c3, a[1][0], a[1][1], a[1][2], a[1][3], B0.z, B0.w);
        mma16816(c0, c1, c2, c3, a[2][0], a[2][1], a[2][2], a[2][3], B1.x, B1.y);
        mma16816(c0, c1, c2, c3, a[3][0], a[3][1], a[3][2], a[3][3], B1.z, B1.w);

        const int code0 = nb * 8 + 2 * q;
        const int code1 = code0 + 1;
        float d00 = fmaf(-2.f, c0, xsq0) + ep.x;
        float d01 = fmaf(-2.f, c1, xsq0) + ep.z;
        float d10 = fmaf(-2.f, c2, xsq1) + ep.x;
        float d11 = fmaf(-2.f, c3, xsq1) + ep.z;
        float b00 = fmaf(xn0, ep.y, ABSL);
        float b01 = fmaf(xn0, ep.w, ABSL);
        float b10 = fmaf(xn1, ep.y, ABSL);
        float b11 = fmaf(xn1, ep.w, ABSL);
        T0 = fminf(T0, d00 + b00); T0 = fminf(T0, d01 + b01);
        T1 = fminf(T1, d10 + b10); T1 = fminf(T1, d11 + b11);
        float l00 = d00 - b00, l01 = d01 - b01;
        float l10 = d10 - b10, l11 = d11 - b11;
        if (l00 < L1a) { if (l00 < L0a) { L1a = L0a; C1a = C0a; L0a = l00; C0a = code0; }
                         else           { L1a = l00; C1a = code0; } }
        if (l01 < L1a) { if (l01 < L0a) { L1a = L0a; C1a = C0a; L0a = l01; C0a = code1; }
                         else           { L1a = l01; C1a = code1; } }
        if (l10 < L1b) { if (l10 < L0b) { L1b = L0b; C1b = C0b; L0b = l10; C0b = code0; }
                         else           { L1b = l10; C1b = code0; } }
        if (l11 < L1b) { if (l11 < L0b) { L1b = L0b; C1b = C0b; L0b = l11; C0b = code1; }
                         else           { L1b = l11; C1b = code1; } }
    }

    // final per-row thresholds (4 lanes per row: xor 1, 2 over q)
    T0 = fminf(T0, __shfl_xor_sync(0xFFFFFFFFu, T0, 1));
    T0 = fminf(T0, __shfl_xor_sync(0xFFFFFFFFu, T0, 2));
    T1 = fminf(T1, __shfl_xor_sync(0xFFFFFFFFu, T1, 1));
    T1 = fminf(T1, __shfl_xor_sync(0xFFFFFFFFu, T1, 2));

    // exact recheck of top candidate; overflow flag if 2nd-best L <= T
    unsigned long long key0 = ~0ULL, key1 = ~0ULL;
    if (L0a <= T0) {
        float s = 0.f;
        const float* e = cb + (size_t)C0a * DDIM;
        #pragma unroll 8
        for (int d = 0; d < DDIM; ++d) s = fmaf(xs[d * 65 + r0], __ldg(&e[d]), s);
        key0 = enc_key(fmaf(-2.f, s, xsq0) + g_esq[C0a], C0a);
    }
    if (L0b <= T1) {
        float s = 0.f;
        const float* e = cb + (size_t)C0b * DDIM;
        #pragma unroll 8
        for (int d = 0; d < DDIM; ++d) s = fmaf(xs[d * 65 + r1], __ldg(&e[d]), s);
        key1 = enc_key(fmaf(-2.f, s, xsq1) + g_esq[C0b], C0b);
    }
    int f0 = (L1a <= T0) ? 1 : 0;
    int f1 = (L1b <= T1) ? 1 : 0;
    {
        unsigned long long t;
        t = __shfl_xor_sync(0xFFFFFFFFu, key0, 1); if (t < key0) key0 = t;
        t = __shfl_xor_sync(0xFFFFFFFFu, key0, 2); if (t < key0) key0 = t;
        t = __shfl_xor_sync(0xFFFFFFFFu, key1, 1); if (t < key1) key1 = t;
        t = __shfl_xor_sync(0xFFFFFFFFu, key1, 2); if (t < key1) key1 = t;
        f0 |= __shfl_xor_sync(0xFFFFFFFFu, f0, 1);
        f0 |= __shfl_xor_sync(0xFFFFFFFFu, f0, 2);
        f1 |= __shfl_xor_sync(0xFFFFFFFFu, f1, 1);
        f1 |= __shfl_xor_sync(0xFFFFFFFFu, f1, 2);
    }
    if (q == 0) {
        if (f0) { int i = atomicAdd(&scount, 1); sflag[i] = r0; }
        else { int code = (int)(key0 & 0xFFFFFFFFULL); g_idx[p0 + r0] = code; out[p0 + r0] = (float)code; }
        if (f1) { int i = atomicAdd(&scount, 1); sflag[i] = r1; }
        else { int code = (int)(key1 & 0xFFFFFFFFULL); g_idx[p0 + r1] = code; out[p0 + r1] = (float)code; }
    }
    __syncthreads();

    // cooperative exact fallback for flagged points (rare)
    const int nf = scount;
    for (int i = 0; i < nf; ++i) {
        int pl = sflag[i];
        if (tid == 0) skey = ~0ULL;
        __syncthreads();
        float xq = sxsq[pl];
        unsigned long long mk = ~0ULL;
        for (int c = tid * 16; c < tid * 16 + 16; ++c) {
            float s = 0.f;
            const float* e = cb + (size_t)c * DDIM;
            #pragma unroll 8
            for (int d = 0; d < DDIM; ++d) s = fmaf(xs[d * 65 + pl], __ldg(&e[d]), s);
            unsigned long long kk = enc_key(fmaf(-2.f, s, xq) + g_esq[c], c);
            if (kk < mk) mk = kk;
        }
        atomicMin(&skey, mk);
        __syncthreads();
        if (tid == 0) {
            int code = (int)(skey & 0xFFFFFFFFULL);
            g_idx[p0 + pl] = code;
            out[p0 + pl] = (float)code;
        }
        __syncthreads();
    }
}

// ---------------------------------------------------------------------------
// Gather: block = (b, 64-point hw chunk); coalesced stores, cached cb reads
// ---------------------------------------------------------------------------
__global__ __launch_bounds__(256)
void gather_kernel(const float* __restrict__ cb, float* __restrict__ out) {
    __shared__ int sidx[64];
    const int tid = threadIdx.x;
    const int b   = blockIdx.x >> 4;
    const int hw0 = (blockIdx.x & 15) * 64;
    if (tid < 64) sidx[tid] = g_idx[b * HW + hw0 + tid];
    __syncthreads();
    const int hw4   = tid & 15;
    const int dbase = tid >> 4;
    const int k0 = sidx[hw4 * 4], k1 = sidx[hw4 * 4 + 1];
    const int k2 = sidx[hw4 * 4 + 2], k3 = sidx[hw4 * 4 + 3];
    #pragma unroll
    for (int it = 0; it < 4; ++it) {
        int d = dbase + it * 16;
        float4 v;
        v.x = __ldg(&cb[k0 * DDIM + d]);
        v.y = __ldg(&cb[k1 * DDIM + d]);
        v.z = __ldg(&cb[k2 * DDIM + d]);
        v.w = __ldg(&cb[k3 * DDIM + d]);
        *reinterpret_cast<float4*>(
            &out[NPTS + (size_t)b * (DDIM * HW) + d * HW + hw0 + hw4 * 4]) = v;
    }
}

extern "C" void kernel_launch(void* const* d_in, const int* in_sizes, int n_in,
                              void* d_out, int out_size) {
    const float* laten = (const float*)d_in[0];   // (32, 64, 32, 32) f32
    const float* cb    = (const float*)d_in[1];   // (2048, 64) f32
    float* out = (float*)d_out;                   // [32768 idx | 2097152 quant]

    prep_epi<<<KCODES / 256, 256>>>(cb);
    prep_bf<<<(NBLK * 32) / 256, 256>>>(cb);
    vq_mma<<<NPTS / PTS_CTA, 128>>>(laten, cb, out);
    gather_kernel<<<(32 * HW) / 64, 256>>>(cb, out);
}

// round 9
// speedup vs baseline: 3.1458x; 3.1458x over previous
#include <cuda_runtime.h>
#include <math.h>
#include <stdint.h>

#define DDIM   64
#define KCODES 2048
#define NPTS   32768
#define HW     1024
#define PTS    128            // points per CTA
#define NB     256            // 8-code blocks
#define XSTR   136            // xs row stride (conflict-free A-frag LDS)
#define CAP    16
#define C1B    2.6e-3f        // dist-level ||x||||e|| coeff (R5-proven)
#define C2B    6.4e-4f        // esq coeff (R5-proven)
#define ABSL   0.03f

__device__ int   g_idx[NPTS];
__device__ float g_esq[KCODES];
__device__ float g_bf[2 * NB * 32 * 20];   // [pass][block][lane][20 words]

static __device__ __forceinline__ float to_tf32(float x) {
    float r; asm("cvt.rna.tf32.f32 %0, %1;" : "=f"(r) : "f"(x)); return r;
}
static __device__ __forceinline__ unsigned long long enc_key(float dist, int code) {
    unsigned int u = __float_as_uint(dist);
    u = (u & 0x80000000u) ? ~u : (u | 0x80000000u);
    return ((unsigned long long)u << 32) | (unsigned)code;
}
static __device__ __forceinline__ void mma8(float& c0, float& c1, float& c2, float& c3,
                                            float a0, float a1, float a2, float a3,
                                            float b0, float b1) {
    asm("mma.sync.aligned.m16n8k8.row.col.f32.tf32.tf32.f32 "
        "{%0,%1,%2,%3}, {%4,%5,%6,%7}, {%8,%9}, {%0,%1,%2,%3};"
        : "+f"(c0), "+f"(c1), "+f"(c2), "+f"(c3)
        : "r"(__float_as_uint(a0)), "r"(__float_as_uint(a1)),
          "r"(__float_as_uint(a2)), "r"(__float_as_uint(a3)),
          "r"(__float_as_uint(b0)), "r"(__float_as_uint(b1)));
}

// ---------------------------------------------------------------------------
// Prep 1: exact esq per code (proven sequential order)
// ---------------------------------------------------------------------------
__global__ void prep_epi(const float* __restrict__ cb) {
    int k = blockIdx.x * blockDim.x + threadIdx.x;
    if (k >= KCODES) return;
    const float4* r = reinterpret_cast<const float4*>(cb + (size_t)k * DDIM);
    float4 v[16];
    #pragma unroll
    for (int i = 0; i < 16; ++i) v[i] = __ldg(&r[i]);
    float s = 0.f;
    #pragma unroll
    for (int i = 0; i < 16; ++i) {
        s = fmaf(v[i].x, v[i].x, s); s = fmaf(v[i].y, v[i].y, s);
        s = fmaf(v[i].z, v[i].z, s); s = fmaf(v[i].w, v[i].w, s);
    }
    g_esq[k] = s;
}

// ---------------------------------------------------------------------------
// Prep 2: pre-swizzled tf32 B fragments for U pass and L pass
// dims 0..63: tf32(e); 64: -h; 65: -l (h+l = esq/2); 66: sgn*(C1/2)*en;
// 67: sgn*((C2/2)*esq + ABSL/2); 68..71: 0.  sgn = -1 (U), +1 (L)
// ---------------------------------------------------------------------------
__global__ void prep_bf(const float* __restrict__ cb) {
    int t = blockIdx.x * blockDim.x + threadIdx.x;    // 0..16383
    int pass = t >> 13;
    int r    = t & 8191;
    int lane = r & 31;
    int nb   = r >> 5;
    int g = lane >> 2, q = lane & 3;
    int code = nb * 8 + g;
    const float* e = cb + (size_t)code * DDIM;
    float esq = g_esq[code];
    float en  = sqrtf(esq);
    float h = to_tf32(0.5f * esq);
    float l = to_tf32(0.5f * esq - h);
    float sgn = pass ? 1.f : -1.f;
    float a66 = to_tf32(sgn * 0.5f * C1B * en);
    float a67 = to_tf32(sgn * (0.5f * C2B * esq + 0.5f * ABSL));

    float w[20];
    #pragma unroll
    for (int s = 0; s < 9; ++s) {
        int kA = s * 8 + q, kB = kA + 4;
        float vA, vB;
        vA = (kA < 64) ? to_tf32(__ldg(&e[kA]))
             : (kA == 64 ? -h : (kA == 65 ? -l : (kA == 66 ? a66 : a67)));
        vB = (kB < 64) ? to_tf32(__ldg(&e[kB]))
             : (kB == 64 ? -h : (kB == 65 ? -l : (kB == 66 ? a66 :
                (kB == 67 ? a67 : 0.f))));
        w[2 * s]     = vA;
        w[2 * s + 1] = vB;
    }
    w[18] = 0.f; w[19] = 0.f;
    float4* dst = reinterpret_cast<float4*>(g_bf + (size_t)t * 20);
    #pragma unroll
    for (int i = 0; i < 5; ++i)
        dst[i] = make_float4(w[4 * i], w[4 * i + 1], w[4 * i + 2], w[4 * i + 3]);
}

// ---------------------------------------------------------------------------
// Main: two tf32 MMA passes + exact recheck. 256 thr = 8 warps x m16.
// ---------------------------------------------------------------------------
__global__ __launch_bounds__(256, 2)
void vq_tf32(const float* __restrict__ laten, const float* __restrict__ cb,
             float* __restrict__ out) {
    __shared__ float xs[DDIM * XSTR];
    __shared__ float sxsq[PTS];
    __shared__ float sxn[PTS];
    __shared__ int   scnt[PTS];
    __shared__ int   scand[PTS][CAP];
    __shared__ int   soflow[PTS];
    __shared__ int   socnt;
    __shared__ unsigned long long skey;

    const int tid  = threadIdx.x;
    const int lane = tid & 31;
    const int w    = tid >> 5;
    const int g = lane >> 2, q = lane & 3;
    const int r0 = w * 16 + g, r1 = r0 + 8;

    const int p0  = blockIdx.x * PTS;
    const int b   = p0 >> 10;
    const int hw0 = p0 & 1023;
    const float* lat_b = laten + (size_t)b * (DDIM * HW) + hw0;

    // stage x tile (float4 in, float4 out; aligned: 544d+16p4 bytes)
    #pragma unroll
    for (int i = 0; i < 8; ++i) {
        int idx = tid + i * 256;               // 2048 float4 groups
        int d = idx >> 5, p4 = idx & 31;
        float4 v = *reinterpret_cast<const float4*>(lat_b + d * HW + p4 * 4);
        *reinterpret_cast<float4*>(&xs[d * XSTR + p4 * 4]) = v;
    }
    if (tid < PTS) scnt[tid] = 0;
    if (tid == 0) socnt = 0;
    __syncthreads();
    if (tid < PTS) {                            // exact xsq, sequential d
        float s = 0.f;
        #pragma unroll 8
        for (int d = 0; d < DDIM; ++d) {
            float v = xs[d * XSTR + tid];
            s = fmaf(v, v, s);
        }
        sxsq[tid] = s;
        sxn[tid]  = to_tf32(sqrtf(s));
    }
    __syncthreads();

    // A fragments (tf32), persistent across both passes
    float a[9][4];
    #pragma unroll
    for (int s = 0; s < 9; ++s) {
        int kA = s * 8 + q, kB = kA + 4;
        float vA0, vA1, vB0, vB1;
        if (kA < 64) { vA0 = to_tf32(xs[kA * XSTR + r0]); vA1 = to_tf32(xs[kA * XSTR + r1]); }
        else if (kA == 66) { vA0 = sxn[r0]; vA1 = sxn[r1]; }
        else { vA0 = 1.f; vA1 = 1.f; }                      // kA in {64,65,67}
        if (kB < 64) { vB0 = to_tf32(xs[kB * XSTR + r0]); vB1 = to_tf32(xs[kB * XSTR + r1]); }
        else if (kB == 66) { vB0 = sxn[r0]; vB1 = sxn[r1]; }
        else if (kB == 67) { vB0 = 1.f; vB1 = 1.f; }
        else { vB0 = 0.f; vB1 = 0.f; }                      // kB >= 68
        a[s][0] = vA0; a[s][1] = vA1; a[s][2] = vB0; a[s][3] = vB1;
    }

    float M0 = -3.402823e+38f, M1 = -3.402823e+38f;

    // ---- Pass U: M = max dotU (epilogue = 4 FMNMX) ----
    {
        const float* base = g_bf + (size_t)lane * 20;
        float4 bufA[5], bufB[5];
        #pragma unroll
        for (int i = 0; i < 5; ++i)
            bufA[i] = __ldg(reinterpret_cast<const float4*>(base) + i);
        for (int nb = 0; nb < NB; nb += 2) {
            #pragma unroll
            for (int i = 0; i < 5; ++i)
                bufB[i] = __ldg(reinterpret_cast<const float4*>(base + (size_t)(nb + 1) * 640) + i);
            {
                const float* wv = reinterpret_cast<const float*>(bufA);
                float c0 = 0.f, c1 = 0.f, c2 = 0.f, c3 = 0.f;
                #pragma unroll
                for (int s = 0; s < 9; ++s)
                    mma8(c0, c1, c2, c3, a[s][0], a[s][1], a[s][2], a[s][3],
                         wv[2 * s], wv[2 * s + 1]);
                M0 = fmaxf(M0, fmaxf(c0, c1));
                M1 = fmaxf(M1, fmaxf(c2, c3));
            }
            if (nb + 2 < NB) {
                #pragma unroll
                for (int i = 0; i < 5; ++i)
                    bufA[i] = __ldg(reinterpret_cast<const float4*>(base + (size_t)(nb + 2) * 640) + i);
            }
            {
                const float* wv = reinterpret_cast<const float*>(bufB);
                float c0 = 0.f, c1 = 0.f, c2 = 0.f, c3 = 0.f;
                #pragma unroll
                for (int s = 0; s < 9; ++s)
                    mma8(c0, c1, c2, c3, a[s][0], a[s][1], a[s][2], a[s][3],
                         wv[2 * s], wv[2 * s + 1]);
                M0 = fmaxf(M0, fmaxf(c0, c1));
                M1 = fmaxf(M1, fmaxf(c2, c3));
            }
        }
    }
    // reduce M across the 4 q-lanes per point
    M0 = fmaxf(M0, __shfl_xor_sync(0xFFFFFFFFu, M0, 1));
    M0 = fmaxf(M0, __shfl_xor_sync(0xFFFFFFFFu, M0, 2));
    M1 = fmaxf(M1, __shfl_xor_sync(0xFFFFFFFFu, M1, 1));
    M1 = fmaxf(M1, __shfl_xor_sync(0xFFFFFFFFu, M1, 2));

    // ---- Pass L: candidates where dotL >= M (epilogue = 4 setp + rare push) ----
    {
        const float* base = g_bf + (size_t)NB * 32 * 20 + (size_t)lane * 20;
        float4 bufA[5], bufB[5];
        #pragma unroll
        for (int i = 0; i < 5; ++i)
            bufA[i] = __ldg(reinterpret_cast<const float4*>(base) + i);
        for (int nb = 0; nb < NB; nb += 2) {
            #pragma unroll
            for (int i = 0; i < 5; ++i)
                bufB[i] = __ldg(reinterpret_cast<const float4*>(base + (size_t)(nb + 1) * 640) + i);
            {
                const float* wv = reinterpret_cast<const float*>(bufA);
                float c0 = 0.f, c1 = 0.f, c2 = 0.f, c3 = 0.f;
                #pragma unroll
                for (int s = 0; s < 9; ++s)
                    mma8(c0, c1, c2, c3, a[s][0], a[s][1], a[s][2], a[s][3],
                         wv[2 * s], wv[2 * s + 1]);
                int code0 = nb * 8 + 2 * q;
                if (c0 >= M0) { int i = atomicAdd(&scnt[r0], 1); if (i < CAP) scand[r0][i] = code0; }
                if (c1 >= M0) { int i = atomicAdd(&scnt[r0], 1); if (i < CAP) scand[r0][i] = code0 + 1; }
                if (c2 >= M1) { int i = atomicAdd(&scnt[r1], 1); if (i < CAP) scand[r1][i] = code0; }
                if (c3 >= M1) { int i = atomicAdd(&scnt[r1], 1); if (i < CAP) scand[r1][i] = code0 + 1; }
            }
            if (nb + 2 < NB) {
                #pragma unroll
                for (int i = 0; i < 5; ++i)
                    bufA[i] = __ldg(reinterpret_cast<const float4*>(base + (size_t)(nb + 2) * 640) + i);
            }
            {
                const float* wv = reinterpret_cast<const float*>(bufB);
                float c0 = 0.f, c1 = 0.f, c2 = 0.f, c3 = 0.f;
                #pragma unroll
                for (int s = 0; s < 9; ++s)
                    mma8(c0, c1, c2, c3, a[s][0], a[s][1], a[s][2], a[s][3],
                         wv[2 * s], wv[2 * s + 1]);
                int code0 = (nb + 1) * 8 + 2 * q;
                if (c0 >= M0) { int i = atomicAdd(&scnt[r0], 1); if (i < CAP) scand[r0][i] = code0; }
                if (c1 >= M0) { int i = atomicAdd(&scnt[r0], 1); if (i < CAP) scand[r0][i] = code0 + 1; }
                if (c2 >= M1) { int i = atomicAdd(&scnt[r1], 1); if (i < CAP) scand[r1][i] = code0; }
                if (c3 >= M1) { int i = atomicAdd(&scnt[r1], 1); if (i < CAP) scand[r1][i] = code0 + 1; }
            }
        }
    }
    __syncthreads();

    // ---- exact recheck (proven fp32 formula) ----
    if (tid < PTS) {
        int n = scnt[tid];
        if (n >= 1 && n <= CAP) {
            float xq = sxsq[tid];
            unsigned long long best = ~0ULL;
            for (int i = 0; i < n; ++i) {
                int code = scand[tid][i];
                const float* e = cb + (size_t)code * DDIM;
                float s = 0.f;
                #pragma unroll 8
                for (int d = 0; d < DDIM; ++d)
                    s = fmaf(xs[d * XSTR + tid], __ldg(&e[d]), s);
                unsigned long long kk = enc_key(fmaf(-2.f, s, xq) + g_esq[code], code);
                if (kk < best) best = kk;
            }
            int code = (int)(best & 0xFFFFFFFFULL);
            g_idx[p0 + tid] = code;
            out[p0 + tid]   = (float)code;
        } else {
            int i = atomicAdd(&socnt, 1);
            soflow[i] = tid;
        }
    }
    __syncthreads();

    // ---- cooperative exact fallback (prob ~0) ----
    const int nf = socnt;
    for (int i = 0; i < nf; ++i) {
        int pl = soflow[i];
        if (tid == 0) skey = ~0ULL;
        __syncthreads();
        float xq = sxsq[pl];
        unsigned long long mk = ~0ULL;
        for (int c = tid * 8; c < tid * 8 + 8; ++c) {
            const float* e = cb + (size_t)c * DDIM;
            float s = 0.f;
            #pragma unroll 8
            for (int d = 0; d < DDIM; ++d)
                s = fmaf(xs[d * XSTR + pl], __ldg(&e[d]), s);
            unsigned long long kk = enc_key(fmaf(-2.f, s, xq) + g_esq[c], c);
            if (kk < mk) mk = kk;
        }
        atomicMin(&skey, mk);
        __syncthreads();
        if (tid == 0) {
            int code = (int)(skey & 0xFFFFFFFFULL);
            g_idx[p0 + pl] = code;
            out[p0 + pl]   = (float)code;
        }
        __syncthreads();
    }
}

// ---------------------------------------------------------------------------
// Gather: coalesced stores, cached cb reads (R8 version, 9.6us)
// ---------------------------------------------------------------------------
__global__ __launch_bounds__(256)
void gather_kernel(const float* __restrict__ cb, float* __restrict__ out) {
    __shared__ int sidx[64];
    const int tid = threadIdx.x;
    const int b   = blockIdx.x >> 4;
    const int hw0 = (blockIdx.x & 15) * 64;
    if (tid < 64) sidx[tid] = g_idx[b * HW + hw0 + tid];
    __syncthreads();
    const int hw4   = tid & 15;
    const int dbase = tid >> 4;
    const int k0 = sidx[hw4 * 4], k1 = sidx[hw4 * 4 + 1];
    const int k2 = sidx[hw4 * 4 + 2], k3 = sidx[hw4 * 4 + 3];
    #pragma unroll
    for (int it = 0; it < 4; ++it) {
        int d = dbase + it * 16;
        float4 v;
        v.x = __ldg(&cb[k0 * DDIM + d]);
        v.y = __ldg(&cb[k1 * DDIM + d]);
        v.z = __ldg(&cb[k2 * DDIM + d]);
        v.w = __ldg(&cb[k3 * DDIM + d]);
        *reinterpret_cast<float4*>(
            &out[NPTS + (size_t)b * (DDIM * HW) + d * HW + hw0 + hw4 * 4]) = v;
    }
}

extern "C" void kernel_launch(void* const* d_in, const int* in_sizes, int n_in,
                              void* d_out, int out_size) {
    const float* laten = (const float*)d_in[0];   // (32, 64, 32, 32) f32
    const float* cb    = (const float*)d_in[1];   // (2048, 64) f32
    float* out = (float*)d_out;                   // [32768 idx | 2097152 quant]

    prep_epi<<<KCODES / 256, 256>>>(cb);
    prep_bf<<<(2 * NB * 32) / 256, 256>>>(cb);
    vq_tf32<<<NPTS / PTS, 256>>>(laten, cb, out);
    gather_kernel<<<(32 * HW) / 64, 256>>>(cb, out);
}